// round 7
// baseline (speedup 1.0000x reference)
#include <cuda_runtime.h>
#include <cuda_bf16.h>
#include <mma.h>
#include <cstdint>

using namespace nvcuda;

// ============================================================================
// out[M,N] = ((x+66)*0.03) @ ((y-160)*0.025),  x,y delivered as int32.
// Minimal-surface path: A = bf16(x+66), B = bf16(y-160) — both integer-valued
// and EXACT in bf16 (|v| < 256). wmma bf16 16x16x16, fp32 accum (rounding
// ~1e-5 rel). No zero-point decomposition, no row/col sums, no transpose,
// no hand fragment layouts, no smem epilogue. Scale once, store direct.
// ============================================================================

static constexpr int MSZ = 4096, NSZ = 4096, KSZ = 4096;
static constexpr int BM = 128, BN = 128, BK = 32;
static constexpr int STAGES = 4;
static constexpr int NITER = KSZ / BK;              // 128
static constexpr float OUT_SCALE = 0.03f * 0.025f;  // 7.5e-4

// smem strides in BYTES (A row = 64B data, B row = 256B data)
static constexpr int APAD_B = 80;                   // 40 bf16 (ldm mult of 8)
static constexpr int BPAD_B = 272;                  // 136 bf16
static constexpr int A_ST = BM * APAD_B;            // 10240
static constexpr int B_ST = BK * BPAD_B;            // 8704
static constexpr int STAGE_B = A_ST + B_ST;         // 18944
static constexpr int SMEM_BYTES = STAGES * STAGE_B; // 75776

// Scratch (__device__ globals: allocation-free rule)
__device__ __align__(16) __nv_bfloat16 g_A16[(size_t)MSZ * KSZ];  // x+66, [M,K]
__device__ __align__(16) __nv_bfloat16 g_B16[(size_t)KSZ * NSZ];  // y-160, [K,N]

#define DINLINE __device__ __forceinline__

DINLINE uint32_t smem_u32(const void* p) {
    uint32_t a;
    asm("{ .reg .u64 t; cvta.to.shared.u64 t, %1; cvt.u32.u64 %0, t; }" : "=r"(a) : "l"(p));
    return a;
}
DINLINE void cp_async16(uint32_t dst, const void* src) {
    asm volatile("cp.async.cg.shared.global [%0], [%1], 16;" :: "r"(dst), "l"(src) : "memory");
}
DINLINE void cp_commit() { asm volatile("cp.async.commit_group;" ::: "memory"); }
DINLINE void cp_wait2()  { asm volatile("cp.async.wait_group 2;" ::: "memory"); }

// ---------------------------------------------------------------------------
// Convert kernels: int32 -> integer-valued bf16 (exact), same layout as input
// ---------------------------------------------------------------------------
__global__ void cvt_kernel(const int4* __restrict__ in, uint2* __restrict__ o,
                           int add, int n4) {
    int stride = gridDim.x * blockDim.x;
    for (int i = blockIdx.x * blockDim.x + threadIdx.x; i < n4; i += stride) {
        int4 v = in[i];
        __nv_bfloat162 p0 = __floats2bfloat162_rn((float)(v.x + add), (float)(v.y + add));
        __nv_bfloat162 p1 = __floats2bfloat162_rn((float)(v.z + add), (float)(v.w + add));
        uint2 w;
        w.x = reinterpret_cast<uint32_t&>(p0);
        w.y = reinterpret_cast<uint32_t&>(p1);
        o[i] = w;
    }
}

// ---------------------------------------------------------------------------
// GEMM: 128x128 tile / CTA, BK=32, 4-stage cp.async, wmma bf16 16x16x16.
// 8 warps 2(m) x 4(n) -> 64x32 warp tile = 4x2 fragments.
// A smem: [128 rows][APAD_B] (row m, k contiguous).
// B smem: [32 rows][BPAD_B]  (row k, n contiguous) — y's native layout.
// ---------------------------------------------------------------------------
__global__ __launch_bounds__(256, 2)
void gemm_kernel(const __nv_bfloat16* __restrict__ A,
                 const __nv_bfloat16* __restrict__ B,
                 float* __restrict__ out) {
    extern __shared__ __align__(128) char smem[];
    uint32_t sb = smem_u32(smem);

    const int tid = threadIdx.x, wid = tid >> 5;
    const int wm = wid & 1, wn = wid >> 1;
    const int bm = blockIdx.y * BM, bn = blockIdx.x * BN;

    const char* gA = (const char*)(A + (size_t)bm * KSZ);   // rows m, k contig
    const char* gB = (const char*)(B + bn);                  // rows k, n contig

    // per-stage producer: A 512 16B-chunks (128 rows x 4), B 512 (32 rows x 16)
    auto issue = [&](int it) {
        int s = it & 3;
        uint32_t sA = sb + s * STAGE_B, sB = sA + A_ST;
#pragma unroll
        for (int j = 0; j < 2; j++) {
            int ch = tid + 256 * j;
            int r = ch >> 2, c = ch & 3;                // m-row, 16B k-chunk
            cp_async16(sA + r * APAD_B + c * 16,
                       gA + (size_t)r * (KSZ * 2) + it * (BK * 2) + c * 16);
        }
#pragma unroll
        for (int j = 0; j < 2; j++) {
            int ch = tid + 256 * j;
            int r = ch >> 4, c = ch & 15;               // k-row, 16B n-chunk
            cp_async16(sB + r * BPAD_B + c * 16,
                       gB + (size_t)(it * BK + r) * (NSZ * 2) + c * 16);
        }
        cp_commit();
    };

    for (int it = 0; it < STAGES - 1; it++) issue(it);

    wmma::fragment<wmma::accumulator, 16, 16, 16, float> acc[4][2];
#pragma unroll
    for (int i = 0; i < 4; i++)
#pragma unroll
        for (int j = 0; j < 2; j++) wmma::fill_fragment(acc[i][j], 0.0f);

    for (int it = 0; it < NITER; ++it) {
        cp_wait2();
        __syncthreads();
        if (it + STAGES - 1 < NITER) issue(it + STAGES - 1);
        else cp_commit();

        int s = it & 3;
        const __nv_bfloat16* sA = (const __nv_bfloat16*)(smem + s * STAGE_B);
        const __nv_bfloat16* sB = (const __nv_bfloat16*)(smem + s * STAGE_B + A_ST);
#pragma unroll
        for (int ks = 0; ks < 2; ks++) {
            wmma::fragment<wmma::matrix_a, 16, 16, 16, __nv_bfloat16, wmma::row_major> af[4];
            wmma::fragment<wmma::matrix_b, 16, 16, 16, __nv_bfloat16, wmma::row_major> bf[2];
#pragma unroll
            for (int fm = 0; fm < 4; fm++)
                wmma::load_matrix_sync(af[fm],
                    sA + (size_t)(wm * 64 + fm * 16) * (APAD_B / 2) + ks * 16,
                    APAD_B / 2);
#pragma unroll
            for (int fn = 0; fn < 2; fn++)
                wmma::load_matrix_sync(bf[fn],
                    sB + (size_t)(ks * 16) * (BPAD_B / 2) + wn * 32 + fn * 16,
                    BPAD_B / 2);
#pragma unroll
            for (int fm = 0; fm < 4; fm++)
#pragma unroll
                for (int fn = 0; fn < 2; fn++)
                    wmma::mma_sync(acc[fm][fn], af[fm], bf[fn], acc[fm][fn]);
        }
    }

    // Epilogue: scale in-fragment, store straight to gmem (layout-free).
#pragma unroll
    for (int fm = 0; fm < 4; fm++)
#pragma unroll
        for (int fn = 0; fn < 2; fn++) {
#pragma unroll
            for (int e = 0; e < acc[fm][fn].num_elements; e++)
                acc[fm][fn].x[e] *= OUT_SCALE;
            wmma::store_matrix_sync(
                out + (size_t)(bm + wm * 64 + fm * 16) * NSZ + bn + wn * 32 + fn * 16,
                acc[fm][fn], NSZ, wmma::mem_row_major);
        }
}

// ---------------------------------------------------------------------------
// Launch
// ---------------------------------------------------------------------------
extern "C" void kernel_launch(void* const* d_in, const int* in_sizes, int n_in,
                              void* d_out, int out_size) {
    const int* x = (const int*)d_in[0];   // [M,K] int32, int8-range
    const int* y = (const int*)d_in[1];   // [K,N] int32, uint8-range
    float* out = (float*)d_out;

    void *pa, *pb;
    cudaGetSymbolAddress(&pa, g_A16);
    cudaGetSymbolAddress(&pb, g_B16);

    cvt_kernel<<<2048, 256>>>((const int4*)x, (uint2*)pa, 66,   (MSZ * KSZ) / 4);
    cvt_kernel<<<2048, 256>>>((const int4*)y, (uint2*)pb, -160, (KSZ * NSZ) / 4);

    cudaFuncSetAttribute(gemm_kernel, cudaFuncAttributeMaxDynamicSharedMemorySize, SMEM_BYTES);
    gemm_kernel<<<dim3(NSZ / BN, MSZ / BM), 256, SMEM_BYTES>>>(
        (const __nv_bfloat16*)pa, (const __nv_bfloat16*)pb, out);
}